// round 2
// baseline (speedup 1.0000x reference)
#include <cuda_runtime.h>
#include <cstdint>

#define NQ_H 32
#define NKV_H 8
#define DIMSZ 4096
#define HDIM 128
#define BSZ 2
#define SLEN 2048
#define MTOT (BSZ * SLEN)      /* 4096 rows */
#define KVDIM (NKV_H * HDIM)   /* 1024 */

// ---------------- scratch (device globals: allocation-free rule) ----------
__device__ float g_q[(size_t)MTOT * DIMSZ];   // 64 MB
__device__ float g_k[(size_t)MTOT * KVDIM];   // 16 MB
__device__ float g_v[(size_t)MTOT * KVDIM];   // 16 MB
__device__ float g_a[(size_t)MTOT * DIMSZ];   // 64 MB

// ---------------- helpers ----------------
__device__ __forceinline__ unsigned f2tf(float f) {
    unsigned r;
    asm("cvt.rna.tf32.f32 %0, %1;" : "=r"(r) : "f"(f));
    return r;
}

__device__ __forceinline__ float fexp2(float x) {
    float y;
    asm("ex2.approx.f32 %0, %1;" : "=f"(y) : "f"(x));
    return y;
}

// D += A(16x8, tf32 row) * B(8x8, tf32 col)
__device__ __forceinline__ void mma_tf32(float c[4], const unsigned a[4], const unsigned b[2]) {
    asm volatile(
        "mma.sync.aligned.m16n8k8.row.col.f32.tf32.tf32.f32 "
        "{%0,%1,%2,%3}, {%4,%5,%6,%7}, {%8,%9}, {%0,%1,%2,%3};"
        : "+f"(c[0]), "+f"(c[1]), "+f"(c[2]), "+f"(c[3])
        : "r"(a[0]), "r"(a[1]), "r"(a[2]), "r"(a[3]), "r"(b[0]), "r"(b[1]));
}

// ---------------- generic GEMM: C[M,N] = A[M,K] @ W[K,N] + bias ----------
// block tile 128x128, 256 threads (8 warps as 2x4), warp tile 64x32, ktile 32
__global__ __launch_bounds__(256) void gemm_bias_tf32(
    const float* __restrict__ A, const float* __restrict__ W,
    const float* __restrict__ bias, float* __restrict__ C,
    int M, int N, int K)
{
    __shared__ float As[128][36];   // 32 k-cols + pad
    __shared__ float Bs[32][132];   // 128 n-cols + pad

    const int tid  = threadIdx.x;
    const int lane = tid & 31;
    const int warp = tid >> 5;
    const int g    = lane >> 2;     // groupID (row within mma)
    const int t4   = lane & 3;      // thread in group
    const int wm   = (warp & 1) * 64;
    const int wn   = (warp >> 1) * 32;
    const int bm   = blockIdx.y * 128;
    const int bn   = blockIdx.x * 128;

    float cf[4][4][4];
#pragma unroll
    for (int i = 0; i < 4; i++)
#pragma unroll
        for (int j = 0; j < 4; j++)
#pragma unroll
            for (int r = 0; r < 4; r++) cf[i][j][r] = 0.0f;

    for (int kt = 0; kt < K; kt += 32) {
        // load A tile 128x32 (16 floats / thread)
#pragma unroll
        for (int i = 0; i < 4; i++) {
            int idx = tid + i * 256;
            int r = idx >> 3, c = (idx & 7) * 4;
            float4 v = *(const float4*)&A[(size_t)(bm + r) * K + kt + c];
            *(float4*)&As[r][c] = v;
        }
        // load B tile 32x128
#pragma unroll
        for (int i = 0; i < 4; i++) {
            int idx = tid + i * 256;
            int r = idx >> 5, c = (idx & 31) * 4;
            float4 v = *(const float4*)&W[(size_t)(kt + r) * N + bn + c];
            *(float4*)&Bs[r][c] = v;
        }
        __syncthreads();

#pragma unroll
        for (int ks = 0; ks < 32; ks += 8) {
            unsigned af[4][4], bf[4][2];
#pragma unroll
            for (int i = 0; i < 4; i++) {
                int rb = wm + i * 16;
                af[i][0] = f2tf(As[rb + g][ks + t4]);
                af[i][1] = f2tf(As[rb + g + 8][ks + t4]);
                af[i][2] = f2tf(As[rb + g][ks + t4 + 4]);
                af[i][3] = f2tf(As[rb + g + 8][ks + t4 + 4]);
            }
#pragma unroll
            for (int j = 0; j < 4; j++) {
                int nb = wn + j * 8;
                bf[j][0] = f2tf(Bs[ks + t4][nb + g]);
                bf[j][1] = f2tf(Bs[ks + t4 + 4][nb + g]);
            }
#pragma unroll
            for (int i = 0; i < 4; i++)
#pragma unroll
                for (int j = 0; j < 4; j++)
                    mma_tf32(cf[i][j], af[i], bf[j]);
        }
        __syncthreads();
    }

    // epilogue: bias + store
#pragma unroll
    for (int i = 0; i < 4; i++) {
        int row0 = bm + wm + i * 16 + g;
        int row1 = row0 + 8;
#pragma unroll
        for (int j = 0; j < 4; j++) {
            int col = bn + wn + j * 8 + 2 * t4;
            float b0 = bias[col], b1 = bias[col + 1];
            float2 v0 = make_float2(cf[i][j][0] + b0, cf[i][j][1] + b1);
            float2 v1 = make_float2(cf[i][j][2] + b0, cf[i][j][3] + b1);
            *(float2*)&C[(size_t)row0 * N + col] = v0;
            *(float2*)&C[(size_t)row1 * N + col] = v1;
        }
    }
}

// ---------------- flash attention (tf32 mma, online softmax) -------------
// q-tile 64 (4 warps x 16 rows), key-tile 32, d = 128
#define QTILE 64
#define KTILE 32
#define ATT_SMEM_FLOATS (QTILE * 132 + 2 * KTILE * 132 + 64 * 36)

__global__ __launch_bounds__(128) void attn_tf32(
    const float* __restrict__ Qp, const float* __restrict__ Kp,
    const float* __restrict__ Vp, float* __restrict__ Op)
{
    extern __shared__ float sm[];
    float (*Qs)[132] = (float(*)[132])sm;                         // 64 x 128
    float (*Ks)[132] = (float(*)[132])(sm + QTILE * 132);         // 32 x 128
    float (*Vs)[132] = (float(*)[132])(sm + QTILE * 132 + KTILE * 132);
    float (*Ps)[36]  = (float(*)[36])(sm + QTILE * 132 + 2 * KTILE * 132); // 64 x 32

    const int tid  = threadIdx.x;
    const int lane = tid & 31;
    const int warp = tid >> 5;
    const int g    = lane >> 2;
    const int t4   = lane & 3;
    const int h    = blockIdx.y;         // q head
    const int b    = blockIdx.z;
    const int q0   = blockIdx.x * QTILE;
    const int kvh  = h >> 2;             // FACTOR = 4
    const int w16  = warp * 16;

    // fold 1/sqrt(128) * log2(e) into Q so we can use ex2 directly
    const float qscale = 0.08838834764831845f * 1.4426950408889634f;

    // load Q tile (pre-scaled)
#pragma unroll
    for (int i = 0; i < 16; i++) {
        int idx = tid + i * 128;
        int r = idx >> 5, c = (idx & 31) * 4;
        float4 v = *(const float4*)&Qp[((size_t)((b * SLEN + q0 + r) * NQ_H) + h) * HDIM + c];
        v.x *= qscale; v.y *= qscale; v.z *= qscale; v.w *= qscale;
        *(float4*)&Qs[r][c] = v;
    }

    float of[16][4];
#pragma unroll
    for (int i = 0; i < 16; i++)
#pragma unroll
        for (int r = 0; r < 4; r++) of[i][r] = 0.0f;
    float m0 = -1e30f, m1 = -1e30f, l0 = 0.0f, l1 = 0.0f;

    for (int kt = 0; kt < SLEN / KTILE; kt++) {
        const int k0 = kt * KTILE;
        __syncthreads();
        // load K,V tiles 32x128 each
#pragma unroll
        for (int i = 0; i < 8; i++) {
            int idx = tid + i * 128;
            int r = idx >> 5, c = (idx & 31) * 4;
            size_t base = ((size_t)((b * SLEN + k0 + r) * NKV_H) + kvh) * HDIM + c;
            *(float4*)&Ks[r][c] = *(const float4*)&Kp[base];
            *(float4*)&Vs[r][c] = *(const float4*)&Vp[base];
        }
        __syncthreads();

        // S = Q(16x128) . K^T(128x32)  -> sf[nb 0..3][4]
        float sf[4][4];
#pragma unroll
        for (int nb = 0; nb < 4; nb++)
#pragma unroll
            for (int r = 0; r < 4; r++) sf[nb][r] = 0.0f;

#pragma unroll
        for (int ks = 0; ks < 16; ks++) {
            int k = ks * 8;
            unsigned af[4];
            af[0] = f2tf(Qs[w16 + g][k + t4]);
            af[1] = f2tf(Qs[w16 + g + 8][k + t4]);
            af[2] = f2tf(Qs[w16 + g][k + t4 + 4]);
            af[3] = f2tf(Qs[w16 + g + 8][k + t4 + 4]);
#pragma unroll
            for (int nb = 0; nb < 4; nb++) {
                unsigned bf[2];
                bf[0] = f2tf(Ks[nb * 8 + g][k + t4]);
                bf[1] = f2tf(Ks[nb * 8 + g][k + t4 + 4]);
                mma_tf32(sf[nb], af, bf);
            }
        }

        // online softmax (exp2 domain). rows r0 = w16+g, r1 = r0+8.
        float mx0 = -1e30f, mx1 = -1e30f;
#pragma unroll
        for (int nb = 0; nb < 4; nb++) {
            mx0 = fmaxf(mx0, fmaxf(sf[nb][0], sf[nb][1]));
            mx1 = fmaxf(mx1, fmaxf(sf[nb][2], sf[nb][3]));
        }
        mx0 = fmaxf(mx0, __shfl_xor_sync(0xffffffffu, mx0, 1));
        mx0 = fmaxf(mx0, __shfl_xor_sync(0xffffffffu, mx0, 2));
        mx1 = fmaxf(mx1, __shfl_xor_sync(0xffffffffu, mx1, 1));
        mx1 = fmaxf(mx1, __shfl_xor_sync(0xffffffffu, mx1, 2));

        float nm0 = fmaxf(m0, mx0), nm1 = fmaxf(m1, mx1);
        float sc0 = fexp2(m0 - nm0), sc1 = fexp2(m1 - nm1);

        float rs0 = 0.0f, rs1 = 0.0f;
#pragma unroll
        for (int nb = 0; nb < 4; nb++) {
            sf[nb][0] = fexp2(sf[nb][0] - nm0);
            sf[nb][1] = fexp2(sf[nb][1] - nm0);
            sf[nb][2] = fexp2(sf[nb][2] - nm1);
            sf[nb][3] = fexp2(sf[nb][3] - nm1);
            rs0 += sf[nb][0] + sf[nb][1];
            rs1 += sf[nb][2] + sf[nb][3];
        }
        rs0 += __shfl_xor_sync(0xffffffffu, rs0, 1);
        rs0 += __shfl_xor_sync(0xffffffffu, rs0, 2);
        rs1 += __shfl_xor_sync(0xffffffffu, rs1, 1);
        rs1 += __shfl_xor_sync(0xffffffffu, rs1, 2);

        l0 = l0 * sc0 + rs0;
        l1 = l1 * sc1 + rs1;
        m0 = nm0; m1 = nm1;

#pragma unroll
        for (int i = 0; i < 16; i++) {
            of[i][0] *= sc0; of[i][1] *= sc0;
            of[i][2] *= sc1; of[i][3] *= sc1;
        }

        // stage P through per-warp smem (C-layout -> A-layout)
#pragma unroll
        for (int nb = 0; nb < 4; nb++) {
            Ps[w16 + g][nb * 8 + 2 * t4]         = sf[nb][0];
            Ps[w16 + g][nb * 8 + 2 * t4 + 1]     = sf[nb][1];
            Ps[w16 + g + 8][nb * 8 + 2 * t4]     = sf[nb][2];
            Ps[w16 + g + 8][nb * 8 + 2 * t4 + 1] = sf[nb][3];
        }
        __syncwarp();

        // O += P(16x32) . V(32x128)
#pragma unroll
        for (int kk = 0; kk < 4; kk++) {
            int k = kk * 8;
            unsigned af[4];
            af[0] = f2tf(Ps[w16 + g][k + t4]);
            af[1] = f2tf(Ps[w16 + g + 8][k + t4]);
            af[2] = f2tf(Ps[w16 + g][k + t4 + 4]);
            af[3] = f2tf(Ps[w16 + g + 8][k + t4 + 4]);
#pragma unroll
            for (int nb2 = 0; nb2 < 16; nb2++) {
                unsigned bf[2];
                bf[0] = f2tf(Vs[k + t4][nb2 * 8 + g]);
                bf[1] = f2tf(Vs[k + t4 + 4][nb2 * 8 + g]);
                mma_tf32(of[nb2], af, bf);
            }
        }
        __syncwarp();
    }

    // epilogue: normalize and store to g_a in [b, s, h, d] layout
    float il0 = 1.0f / l0, il1 = 1.0f / l1;
    int row0 = q0 + w16 + g;
    int row1 = row0 + 8;
#pragma unroll
    for (int nb2 = 0; nb2 < 16; nb2++) {
        int col = nb2 * 8 + 2 * t4;
        size_t i0 = ((size_t)((b * SLEN + row0) * NQ_H) + h) * HDIM + col;
        size_t i1 = ((size_t)((b * SLEN + row1) * NQ_H) + h) * HDIM + col;
        *(float2*)&Op[i0] = make_float2(of[nb2][0] * il0, of[nb2][1] * il0);
        *(float2*)&Op[i1] = make_float2(of[nb2][2] * il1, of[nb2][3] * il1);
    }
}

// ---------------- launcher ----------------
extern "C" void kernel_launch(void* const* d_in, const int* in_sizes, int n_in,
                              void* d_out, int out_size)
{
    const float* x    = (const float*)d_in[0];
    const float* wq_w = (const float*)d_in[1];
    const float* wq_b = (const float*)d_in[2];
    const float* wk_w = (const float*)d_in[3];
    const float* wk_b = (const float*)d_in[4];
    const float* wv_w = (const float*)d_in[5];
    const float* wv_b = (const float*)d_in[6];
    const float* wo_w = (const float*)d_in[7];
    const float* wo_b = (const float*)d_in[8];
    float* out = (float*)d_out;

    float *qp, *kp, *vp, *ap;
    cudaGetSymbolAddress((void**)&qp, g_q);
    cudaGetSymbolAddress((void**)&kp, g_k);
    cudaGetSymbolAddress((void**)&vp, g_v);
    cudaGetSymbolAddress((void**)&ap, g_a);

    // projections
    gemm_bias_tf32<<<dim3(DIMSZ / 128, MTOT / 128), 256>>>(x, wq_w, wq_b, qp, MTOT, DIMSZ, DIMSZ);
    gemm_bias_tf32<<<dim3(KVDIM / 128, MTOT / 128), 256>>>(x, wk_w, wk_b, kp, MTOT, KVDIM, DIMSZ);
    gemm_bias_tf32<<<dim3(KVDIM / 128, MTOT / 128), 256>>>(x, wv_w, wv_b, vp, MTOT, KVDIM, DIMSZ);

    // attention
    const int smem_bytes = ATT_SMEM_FLOATS * (int)sizeof(float);
    cudaFuncSetAttribute(attn_tf32, cudaFuncAttributeMaxDynamicSharedMemorySize, smem_bytes);
    attn_tf32<<<dim3(SLEN / QTILE, NQ_H, BSZ), 128, smem_bytes>>>(qp, kp, vp, ap);

    // output projection
    gemm_bias_tf32<<<dim3(DIMSZ / 128, MTOT / 128), 256>>>(ap, wo_w, wo_b, out, MTOT, DIMSZ, DIMSZ);
}

// round 3
// speedup vs baseline: 1.2354x; 1.2354x over previous
#include <cuda_runtime.h>
#include <cstdint>

#define NQ_H 32
#define NKV_H 8
#define DIMSZ 4096
#define HDIM 128
#define BSZ 2
#define SLEN 2048
#define MTOT (BSZ * SLEN)      /* 4096 rows */
#define KVDIM (NKV_H * HDIM)   /* 1024 */

// ---------------- scratch (device globals: allocation-free rule) ----------
__device__ float g_q[(size_t)MTOT * DIMSZ];   // 64 MB
__device__ float g_k[(size_t)MTOT * KVDIM];   // 16 MB
__device__ float g_v[(size_t)MTOT * KVDIM];   // 16 MB
__device__ float g_a[(size_t)MTOT * DIMSZ];   // 64 MB

// ---------------- helpers ----------------
__device__ __forceinline__ unsigned f2tf(float f) {
    unsigned r;
    asm("cvt.rna.tf32.f32 %0, %1;" : "=r"(r) : "f"(f));
    return r;
}

__device__ __forceinline__ uint4 cvt4(float4 v) {
    uint4 r;
    r.x = f2tf(v.x); r.y = f2tf(v.y); r.z = f2tf(v.z); r.w = f2tf(v.w);
    return r;
}

__device__ __forceinline__ float fexp2(float x) {
    float y;
    asm("ex2.approx.f32 %0, %1;" : "=f"(y) : "f"(x));
    return y;
}

// D += A(16x8, tf32 row) * B(8x8, tf32 col)
__device__ __forceinline__ void mma_tf32(float c[4], const unsigned a[4], const unsigned b[2]) {
    asm volatile(
        "mma.sync.aligned.m16n8k8.row.col.f32.tf32.tf32.f32 "
        "{%0,%1,%2,%3}, {%4,%5,%6,%7}, {%8,%9}, {%0,%1,%2,%3};"
        : "+f"(c[0]), "+f"(c[1]), "+f"(c[2]), "+f"(c[3])
        : "r"(a[0]), "r"(a[1]), "r"(a[2]), "r"(a[3]), "r"(b[0]), "r"(b[1]));
}

// ---------------- generic GEMM: C[M,N] = A[M,K] @ W[K,N] + bias ----------
// block tile 128x128, 256 threads (8 warps as 2x4), warp tile 64x32, ktile 32
// smem holds pre-converted tf32 bits; gmem loads register-staged one tile ahead.
__global__ __launch_bounds__(256) void gemm_bias_tf32(
    const float* __restrict__ A, const float* __restrict__ W,
    const float* __restrict__ bias, float* __restrict__ C,
    int M, int N, int K)
{
    __shared__ unsigned As[128][36];   // 32 k-cols + pad (bank offset 4/row)
    __shared__ unsigned Bs[32][136];   // 128 n-cols + pad (bank offset 8/row)

    const int tid  = threadIdx.x;
    const int lane = tid & 31;
    const int warp = tid >> 5;
    const int g    = lane >> 2;     // groupID (row within mma)
    const int t4   = lane & 3;      // thread in group
    const int wm   = (warp & 1) * 64;
    const int wn   = (warp >> 1) * 32;
    const int bm   = blockIdx.y * 128;
    const int bn   = blockIdx.x * 128;

    float cf[4][4][4];
#pragma unroll
    for (int i = 0; i < 4; i++)
#pragma unroll
        for (int j = 0; j < 4; j++)
#pragma unroll
            for (int r = 0; r < 4; r++) cf[i][j][r] = 0.0f;

    // register staging buffers
    float4 ar[4], br[4];
#pragma unroll
    for (int i = 0; i < 4; i++) {
        int idx = tid + i * 256;
        int r = idx >> 3, c = (idx & 7) * 4;
        ar[i] = *(const float4*)&A[(size_t)(bm + r) * K + c];
    }
#pragma unroll
    for (int i = 0; i < 4; i++) {
        int idx = tid + i * 256;
        int r = idx >> 5, c = (idx & 31) * 4;
        br[i] = *(const float4*)&W[(size_t)r * N + bn + c];
    }

    for (int kt = 0; kt < K; kt += 32) {
        // commit staged tile to smem (convert to tf32 here, once)
#pragma unroll
        for (int i = 0; i < 4; i++) {
            int idx = tid + i * 256;
            int r = idx >> 3, c = (idx & 7) * 4;
            *(uint4*)&As[r][c] = cvt4(ar[i]);
        }
#pragma unroll
        for (int i = 0; i < 4; i++) {
            int idx = tid + i * 256;
            int r = idx >> 5, c = (idx & 31) * 4;
            *(uint4*)&Bs[r][c] = cvt4(br[i]);
        }
        __syncthreads();

        // prefetch next tile into registers (overlaps with compute below)
        if (kt + 32 < K) {
#pragma unroll
            for (int i = 0; i < 4; i++) {
                int idx = tid + i * 256;
                int r = idx >> 3, c = (idx & 7) * 4;
                ar[i] = *(const float4*)&A[(size_t)(bm + r) * K + kt + 32 + c];
            }
#pragma unroll
            for (int i = 0; i < 4; i++) {
                int idx = tid + i * 256;
                int r = idx >> 5, c = (idx & 31) * 4;
                br[i] = *(const float4*)&W[(size_t)(kt + 32 + r) * N + bn + c];
            }
        }

#pragma unroll
        for (int ks = 0; ks < 32; ks += 8) {
            unsigned af[4][4], bf[4][2];
#pragma unroll
            for (int i = 0; i < 4; i++) {
                int rb = wm + i * 16;
                af[i][0] = As[rb + g][ks + t4];
                af[i][1] = As[rb + g + 8][ks + t4];
                af[i][2] = As[rb + g][ks + t4 + 4];
                af[i][3] = As[rb + g + 8][ks + t4 + 4];
            }
#pragma unroll
            for (int j = 0; j < 4; j++) {
                int nb = wn + j * 8;
                bf[j][0] = Bs[ks + t4][nb + g];
                bf[j][1] = Bs[ks + t4 + 4][nb + g];
            }
#pragma unroll
            for (int i = 0; i < 4; i++)
#pragma unroll
                for (int j = 0; j < 4; j++)
                    mma_tf32(cf[i][j], af[i], bf[j]);
        }
        __syncthreads();
    }

    // epilogue: bias + store
#pragma unroll
    for (int i = 0; i < 4; i++) {
        int row0 = bm + wm + i * 16 + g;
        int row1 = row0 + 8;
#pragma unroll
        for (int j = 0; j < 4; j++) {
            int col = bn + wn + j * 8 + 2 * t4;
            float b0 = bias[col], b1 = bias[col + 1];
            float2 v0 = make_float2(cf[i][j][0] + b0, cf[i][j][1] + b1);
            float2 v1 = make_float2(cf[i][j][2] + b0, cf[i][j][3] + b1);
            *(float2*)&C[(size_t)row0 * N + col] = v0;
            *(float2*)&C[(size_t)row1 * N + col] = v1;
        }
    }
}

// ---------------- flash attention (tf32 mma, online softmax) -------------
// q-tile 64 (4 warps x 16 rows), key-tile 32, d = 128
#define QTILE 64
#define KTILE 32
#define QS_STRIDE 132
#define KS_STRIDE 132
#define VS_STRIDE 136
#define PS_STRIDE 36
#define ATT_SMEM_FLOATS (QTILE * QS_STRIDE + KTILE * KS_STRIDE + KTILE * VS_STRIDE + QTILE * PS_STRIDE)

__global__ __launch_bounds__(128) void attn_tf32(
    const float* __restrict__ Qp, const float* __restrict__ Kp,
    const float* __restrict__ Vp, float* __restrict__ Op)
{
    extern __shared__ unsigned sm[];
    unsigned (*Qs)[QS_STRIDE] = (unsigned(*)[QS_STRIDE])sm;                    // 64 x 128 tf32
    unsigned (*Ks)[KS_STRIDE] = (unsigned(*)[KS_STRIDE])(sm + QTILE * QS_STRIDE);
    unsigned (*Vs)[VS_STRIDE] = (unsigned(*)[VS_STRIDE])(sm + QTILE * QS_STRIDE + KTILE * KS_STRIDE);
    unsigned (*Ps)[PS_STRIDE] = (unsigned(*)[PS_STRIDE])(sm + QTILE * QS_STRIDE + KTILE * KS_STRIDE + KTILE * VS_STRIDE);

    const int tid  = threadIdx.x;
    const int lane = tid & 31;
    const int warp = tid >> 5;
    const int g    = lane >> 2;
    const int t4   = lane & 3;
    const int h    = blockIdx.y;         // q head
    const int b    = blockIdx.z;
    const int q0   = blockIdx.x * QTILE;
    const int kvh  = h >> 2;             // FACTOR = 4
    const int w16  = warp * 16;

    // fold 1/sqrt(128) * log2(e) into Q so we can use ex2 directly
    const float qscale = 0.08838834764831845f * 1.4426950408889634f;

    // load Q tile (pre-scaled, pre-converted to tf32)
#pragma unroll
    for (int i = 0; i < 16; i++) {
        int idx = tid + i * 128;
        int r = idx >> 5, c = (idx & 31) * 4;
        float4 v = *(const float4*)&Qp[((size_t)((b * SLEN + q0 + r) * NQ_H) + h) * HDIM + c];
        v.x *= qscale; v.y *= qscale; v.z *= qscale; v.w *= qscale;
        *(uint4*)&Qs[r][c] = cvt4(v);
    }

    float of[16][4];
#pragma unroll
    for (int i = 0; i < 16; i++)
#pragma unroll
        for (int r = 0; r < 4; r++) of[i][r] = 0.0f;
    float m0 = -1e30f, m1 = -1e30f, l0 = 0.0f, l1 = 0.0f;

    for (int kt = 0; kt < SLEN / KTILE; kt++) {
        const int k0 = kt * KTILE;
        __syncthreads();
        // load K,V tiles 32x128 each (convert to tf32 at store)
#pragma unroll
        for (int i = 0; i < 8; i++) {
            int idx = tid + i * 128;
            int r = idx >> 5, c = (idx & 31) * 4;
            size_t base = ((size_t)((b * SLEN + k0 + r) * NKV_H) + kvh) * HDIM + c;
            *(uint4*)&Ks[r][c] = cvt4(*(const float4*)&Kp[base]);
            *(uint4*)&Vs[r][c] = cvt4(*(const float4*)&Vp[base]);
        }
        __syncthreads();

        // S = Q(16x128) . K^T(128x32)  -> sf[nb 0..3][4]
        float sf[4][4];
#pragma unroll
        for (int nb = 0; nb < 4; nb++)
#pragma unroll
            for (int r = 0; r < 4; r++) sf[nb][r] = 0.0f;

#pragma unroll
        for (int ks = 0; ks < 16; ks++) {
            int k = ks * 8;
            unsigned af[4];
            af[0] = Qs[w16 + g][k + t4];
            af[1] = Qs[w16 + g + 8][k + t4];
            af[2] = Qs[w16 + g][k + t4 + 4];
            af[3] = Qs[w16 + g + 8][k + t4 + 4];
#pragma unroll
            for (int nb = 0; nb < 4; nb++) {
                unsigned bf[2];
                bf[0] = Ks[nb * 8 + g][k + t4];
                bf[1] = Ks[nb * 8 + g][k + t4 + 4];
                mma_tf32(sf[nb], af, bf);
            }
        }

        // online softmax (exp2 domain). rows r0 = w16+g, r1 = r0+8.
        float mx0 = -1e30f, mx1 = -1e30f;
#pragma unroll
        for (int nb = 0; nb < 4; nb++) {
            mx0 = fmaxf(mx0, fmaxf(sf[nb][0], sf[nb][1]));
            mx1 = fmaxf(mx1, fmaxf(sf[nb][2], sf[nb][3]));
        }
        mx0 = fmaxf(mx0, __shfl_xor_sync(0xffffffffu, mx0, 1));
        mx0 = fmaxf(mx0, __shfl_xor_sync(0xffffffffu, mx0, 2));
        mx1 = fmaxf(mx1, __shfl_xor_sync(0xffffffffu, mx1, 1));
        mx1 = fmaxf(mx1, __shfl_xor_sync(0xffffffffu, mx1, 2));

        float nm0 = fmaxf(m0, mx0), nm1 = fmaxf(m1, mx1);
        float sc0 = fexp2(m0 - nm0), sc1 = fexp2(m1 - nm1);

        float rs0 = 0.0f, rs1 = 0.0f;
#pragma unroll
        for (int nb = 0; nb < 4; nb++) {
            sf[nb][0] = fexp2(sf[nb][0] - nm0);
            sf[nb][1] = fexp2(sf[nb][1] - nm0);
            sf[nb][2] = fexp2(sf[nb][2] - nm1);
            sf[nb][3] = fexp2(sf[nb][3] - nm1);
            rs0 += sf[nb][0] + sf[nb][1];
            rs1 += sf[nb][2] + sf[nb][3];
        }
        rs0 += __shfl_xor_sync(0xffffffffu, rs0, 1);
        rs0 += __shfl_xor_sync(0xffffffffu, rs0, 2);
        rs1 += __shfl_xor_sync(0xffffffffu, rs1, 1);
        rs1 += __shfl_xor_sync(0xffffffffu, rs1, 2);

        l0 = l0 * sc0 + rs0;
        l1 = l1 * sc1 + rs1;
        m0 = nm0; m1 = nm1;

#pragma unroll
        for (int i = 0; i < 16; i++) {
            of[i][0] *= sc0; of[i][1] *= sc0;
            of[i][2] *= sc1; of[i][3] *= sc1;
        }

        // stage P through per-warp smem (C-layout -> A-layout), pre-converted
#pragma unroll
        for (int nb = 0; nb < 4; nb++) {
            Ps[w16 + g][nb * 8 + 2 * t4]         = f2tf(sf[nb][0]);
            Ps[w16 + g][nb * 8 + 2 * t4 + 1]     = f2tf(sf[nb][1]);
            Ps[w16 + g + 8][nb * 8 + 2 * t4]     = f2tf(sf[nb][2]);
            Ps[w16 + g + 8][nb * 8 + 2 * t4 + 1] = f2tf(sf[nb][3]);
        }
        __syncwarp();

        // O += P(16x32) . V(32x128)
#pragma unroll
        for (int kk = 0; kk < 4; kk++) {
            int k = kk * 8;
            unsigned af[4];
            af[0] = Ps[w16 + g][k + t4];
            af[1] = Ps[w16 + g + 8][k + t4];
            af[2] = Ps[w16 + g][k + t4 + 4];
            af[3] = Ps[w16 + g + 8][k + t4 + 4];
#pragma unroll
            for (int nb2 = 0; nb2 < 16; nb2++) {
                unsigned bf[2];
                bf[0] = Vs[k + t4][nb2 * 8 + g];
                bf[1] = Vs[k + t4 + 4][nb2 * 8 + g];
                mma_tf32(of[nb2], af, bf);
            }
        }
        __syncwarp();
    }

    // epilogue: normalize and store to g_a in [b, s, h, d] layout
    float il0 = 1.0f / l0, il1 = 1.0f / l1;
    int row0 = q0 + w16 + g;
    int row1 = row0 + 8;
#pragma unroll
    for (int nb2 = 0; nb2 < 16; nb2++) {
        int col = nb2 * 8 + 2 * t4;
        size_t i0 = ((size_t)((b * SLEN + row0) * NQ_H) + h) * HDIM + col;
        size_t i1 = ((size_t)((b * SLEN + row1) * NQ_H) + h) * HDIM + col;
        *(float2*)&Op[i0] = make_float2(of[nb2][0] * il0, of[nb2][1] * il0);
        *(float2*)&Op[i1] = make_float2(of[nb2][2] * il1, of[nb2][3] * il1);
    }
}

// ---------------- launcher ----------------
extern "C" void kernel_launch(void* const* d_in, const int* in_sizes, int n_in,
                              void* d_out, int out_size)
{
    const float* x    = (const float*)d_in[0];
    const float* wq_w = (const float*)d_in[1];
    const float* wq_b = (const float*)d_in[2];
    const float* wk_w = (const float*)d_in[3];
    const float* wk_b = (const float*)d_in[4];
    const float* wv_w = (const float*)d_in[5];
    const float* wv_b = (const float*)d_in[6];
    const float* wo_w = (const float*)d_in[7];
    const float* wo_b = (const float*)d_in[8];
    float* out = (float*)d_out;

    float *qp, *kp, *vp, *ap;
    cudaGetSymbolAddress((void**)&qp, g_q);
    cudaGetSymbolAddress((void**)&kp, g_k);
    cudaGetSymbolAddress((void**)&vp, g_v);
    cudaGetSymbolAddress((void**)&ap, g_a);

    // projections
    gemm_bias_tf32<<<dim3(DIMSZ / 128, MTOT / 128), 256>>>(x, wq_w, wq_b, qp, MTOT, DIMSZ, DIMSZ);
    gemm_bias_tf32<<<dim3(KVDIM / 128, MTOT / 128), 256>>>(x, wk_w, wk_b, kp, MTOT, KVDIM, DIMSZ);
    gemm_bias_tf32<<<dim3(KVDIM / 128, MTOT / 128), 256>>>(x, wv_w, wv_b, vp, MTOT, KVDIM, DIMSZ);

    // attention
    const int smem_bytes = ATT_SMEM_FLOATS * (int)sizeof(unsigned);
    cudaFuncSetAttribute(attn_tf32, cudaFuncAttributeMaxDynamicSharedMemorySize, smem_bytes);
    attn_tf32<<<dim3(SLEN / QTILE, NQ_H, BSZ), 128, smem_bytes>>>(qp, kp, vp, ap);

    // output projection
    gemm_bias_tf32<<<dim3(DIMSZ / 128, MTOT / 128), 256>>>(ap, wo_w, wo_b, out, MTOT, DIMSZ, DIMSZ);
}